// round 2
// baseline (speedup 1.0000x reference)
#include <cuda_runtime.h>
#include <cstdint>

static constexpr int B_   = 8;
static constexpr int C_   = 64;
static constexpr int R_   = 32;
static constexpr int R3_  = 32768;   // R^3
static constexpr int NP_  = 32768;   // points per batch

// ---------------- device scratch (no allocations allowed) ----------------
__device__ float g_grid0[(size_t)B_ * R3_ * C_];   // voxelized avg, channels-last [b][vox][c]
__device__ float g_conv1[(size_t)B_ * R3_ * C_];
__device__ float g_conv2[(size_t)B_ * R3_ * C_];
__device__ float g_pbuf [(size_t)B_ * NP_ * C_];   // point branch pre-BN [b][n][c]
__device__ float g_cnt  [(size_t)B_ * R3_];
__device__ float g_nc   [(size_t)B_ * 3 * NP_];    // normalized float voxel coords [b][axis][n]
__device__ int   g_vidx [(size_t)B_ * NP_];
__device__ float g_wt1  [27 * 64 * 64];            // [k][ci][co]
__device__ float g_wt2  [27 * 64 * 64];
__device__ float g_wpt  [64 * 64];                 // [ci][co]
__device__ float g_mean [B_ * 3];
__device__ float g_den  [B_];                      // 2*max_norm
__device__ float g_stats[6 * 64];                  // sum1,sq1,sum2,sq2,sump,sqp
__device__ float g_bn   [6 * 64];                  // scale1,shift1,scale2,shift2,scalep,shiftp

// ---------------- zero scratch that is accumulated into ----------------
__global__ void zero_kernel() {
    size_t i = (size_t)blockIdx.x * blockDim.x + threadIdx.x;
    size_t total = (size_t)B_ * R3_ * C_;
    if (i < total) g_grid0[i] = 0.f;
    if (i < (size_t)B_ * R3_) g_cnt[i] = 0.f;
    if (i < 6 * 64) g_stats[i] = 0.f;
}

// ---------------- weight re-layout ----------------
__global__ void prep_kernel(const float* __restrict__ w1,
                            const float* __restrict__ w2,
                            const float* __restrict__ wp) {
    int i = blockIdx.x * blockDim.x + threadIdx.x;
    if (i < 27 * 64 * 64) {
        int k  = i >> 12;          // /4096
        int ci = (i >> 6) & 63;
        int co = i & 63;
        size_t src = ((size_t)co * 64 + ci) * 27 + k;
        g_wt1[i] = w1[src];
        g_wt2[i] = w2[src];
    }
    if (i < 64 * 64) {
        int ci = i >> 6, co = i & 63;
        g_wpt[i] = wp[co * 64 + ci];
    }
}

// ---------------- per-batch coordinate mean ----------------
__global__ void mean_kernel(const float* __restrict__ coords) {
    int b = blockIdx.x, tid = threadIdx.x;
    float s0 = 0.f, s1 = 0.f, s2 = 0.f;
    for (int n = tid; n < NP_; n += 256) {
        s0 += coords[((size_t)b * 3 + 0) * NP_ + n];
        s1 += coords[((size_t)b * 3 + 1) * NP_ + n];
        s2 += coords[((size_t)b * 3 + 2) * NP_ + n];
    }
    __shared__ float sm[3][256];
    sm[0][tid] = s0; sm[1][tid] = s1; sm[2][tid] = s2;
    __syncthreads();
    for (int o = 128; o > 0; o >>= 1) {
        if (tid < o) {
            sm[0][tid] += sm[0][tid + o];
            sm[1][tid] += sm[1][tid + o];
            sm[2][tid] += sm[2][tid + o];
        }
        __syncthreads();
    }
    if (tid == 0) {
        const float inv = 1.f / (float)NP_;
        g_mean[b * 3 + 0] = sm[0][0] * inv;
        g_mean[b * 3 + 1] = sm[1][0] * inv;
        g_mean[b * 3 + 2] = sm[2][0] * inv;
    }
}

// ---------------- per-batch max norm ----------------
__global__ void maxnorm_kernel(const float* __restrict__ coords) {
    int b = blockIdx.x, tid = threadIdx.x;
    float m0 = g_mean[b * 3], m1 = g_mean[b * 3 + 1], m2 = g_mean[b * 3 + 2];
    float mx = 0.f;
    for (int n = tid; n < NP_; n += 256) {
        float d0 = coords[((size_t)b * 3 + 0) * NP_ + n] - m0;
        float d1 = coords[((size_t)b * 3 + 1) * NP_ + n] - m1;
        float d2 = coords[((size_t)b * 3 + 2) * NP_ + n] - m2;
        float s = d0 * d0 + d1 * d1 + d2 * d2;
        mx = fmaxf(mx, s);
    }
    __shared__ float sm[256];
    sm[tid] = mx;
    __syncthreads();
    for (int o = 128; o > 0; o >>= 1) {
        if (tid < o) sm[tid] = fmaxf(sm[tid], sm[tid + o]);
        __syncthreads();
    }
    if (tid == 0) g_den[b] = 2.f * sqrtf(sm[0]);
}

// ---------------- normalized coords + voxel index + counts ----------------
__global__ void voxelidx_kernel(const float* __restrict__ coords) {
    int i = blockIdx.x * blockDim.x + threadIdx.x;  // B*NP
    int b = i >> 15;
    int n = i & 32767;
    float den = g_den[b];
    int vi[3];
#pragma unroll
    for (int a = 0; a < 3; a++) {
        float c = coords[((size_t)b * 3 + a) * NP_ + n];
        float t = (c - g_mean[b * 3 + a]) / den + 0.5f;
        float v = fminf(fmaxf(t * (float)R_, 0.f), (float)(R_ - 1));
        g_nc[((size_t)b * 3 + a) * NP_ + n] = v;
        vi[a] = (int)rintf(v);          // round half-to-even, matches jnp.round
    }
    int flat = vi[0] * 1024 + vi[1] * 32 + vi[2];
    g_vidx[i] = flat;
    atomicAdd(&g_cnt[(size_t)b * R3_ + flat], 1.f);
}

// ---------------- scatter-add features into grid ----------------
__global__ void scatter_kernel(const float* __restrict__ features) {
    size_t i = (size_t)blockIdx.x * 256 + threadIdx.x;  // B*64*NP, matches features layout
    int n = (int)(i & 32767);
    int c = (int)((i >> 15) & 63);
    int b = (int)(i >> 21);
    int flat = g_vidx[((size_t)b << 15) + n];
    atomicAdd(&g_grid0[(((size_t)b << 15) + flat) * 64 + c], features[i]);
}

// ---------------- divide by counts ----------------
__global__ void avg_kernel() {
    size_t i = (size_t)blockIdx.x * 256 + threadIdx.x;  // B*R3*64
    float cn = g_cnt[i >> 6];
    g_grid0[i] = g_grid0[i] / fmaxf(cn, 1.f);
}

// ---------------- 3x3x3 conv as implicit GEMM ----------------
// in/out channels-last [b][vox][64]. Tile: 128 voxels (fixed x, 4 y's, all z) x 64 co.
// Optional fused BN(scale,shift)+leaky(0.1) applied to the INPUT (for conv2).
__global__ __launch_bounds__(256) void conv3d_kernel(
    const float* __restrict__ in, float* __restrict__ out,
    const float* __restrict__ wt,      // [27][64][64] (k,ci,co)
    const float* __restrict__ bias,    // [64]
    const float* __restrict__ bnscale, // nullptr for conv1
    const float* __restrict__ bnshift) {
    __shared__ float As[16][136];
    __shared__ float Bs[16][64];
    int tile = blockIdx.x;
    int b = tile >> 8;
    int t = tile & 255;
    int x  = t >> 3;
    int y0 = (t & 7) << 2;
    int tid = threadIdx.x;
    int tx = tid & 15;       // co group (4 co)
    int ty = tid >> 4;       // row group (8 rows)
    int lrow  = tid >> 1;    // A-loader row 0..127
    int lhalf = (tid & 1) << 3;
    int ly = y0 + (lrow >> 5);
    int lz = lrow & 31;
    const bool use_bn = (bnscale != nullptr);

    float acc[8][4];
#pragma unroll
    for (int i = 0; i < 8; i++)
#pragma unroll
        for (int j = 0; j < 4; j++) acc[i][j] = 0.f;

    for (int k = 0; k < 27; k++) {
        int dx = k / 9 - 1, dy = (k / 3) % 3 - 1, dz = k % 3 - 1;
        int nx = x + dx, ny = ly + dy, nz = lz + dz;
        bool valid = ((unsigned)nx < 32u) && ((unsigned)ny < 32u) && ((unsigned)nz < 32u);
        const float* src = in + (((size_t)b * R3_) + (size_t)(nx * 1024 + ny * 32 + nz)) * 64;

        for (int c0 = 0; c0 < 64; c0 += 16) {
            // B tile: wt[k][c0+r][:]
            {
                int r  = tid >> 4;
                int cg = (tid & 15) << 2;
                *(float4*)&Bs[r][cg] =
                    *(const float4*)&wt[((size_t)(k * 64 + c0 + r)) * 64 + cg];
            }
            // A tile: 128 rows x 16 ci (shifted, masked, optionally BN+leaky)
            float v[8];
            if (valid) {
                float4 p0 = *(const float4*)&src[c0 + lhalf];
                float4 p1 = *(const float4*)&src[c0 + lhalf + 4];
                v[0] = p0.x; v[1] = p0.y; v[2] = p0.z; v[3] = p0.w;
                v[4] = p1.x; v[5] = p1.y; v[6] = p1.z; v[7] = p1.w;
                if (use_bn) {
#pragma unroll
                    for (int i = 0; i < 8; i++) {
                        float tv = v[i] * bnscale[c0 + lhalf + i] + bnshift[c0 + lhalf + i];
                        v[i] = fmaxf(tv, 0.1f * tv);
                    }
                }
            } else {
#pragma unroll
                for (int i = 0; i < 8; i++) v[i] = 0.f;
            }
#pragma unroll
            for (int i = 0; i < 8; i++) As[lhalf + i][lrow] = v[i];
            __syncthreads();

#pragma unroll
            for (int kk = 0; kk < 16; kk++) {
                float4 a0 = *(const float4*)&As[kk][ty << 3];
                float4 a1 = *(const float4*)&As[kk][(ty << 3) + 4];
                float4 bv = *(const float4*)&Bs[kk][tx << 2];
                float a[8] = {a0.x, a0.y, a0.z, a0.w, a1.x, a1.y, a1.z, a1.w};
                float bb[4] = {bv.x, bv.y, bv.z, bv.w};
#pragma unroll
                for (int i = 0; i < 8; i++)
#pragma unroll
                    for (int j = 0; j < 4; j++) acc[i][j] += a[i] * bb[j];
            }
            __syncthreads();
        }
    }

    float4 b4 = *(const float4*)&bias[tx << 2];
    size_t obase = (((size_t)b * R3_) + (size_t)t * 128) * 64;
#pragma unroll
    for (int i = 0; i < 8; i++) {
        float4 o;
        o.x = acc[i][0] + b4.x;
        o.y = acc[i][1] + b4.y;
        o.z = acc[i][2] + b4.z;
        o.w = acc[i][3] + b4.w;
        *(float4*)&out[obase + (size_t)((ty << 3) + i) * 64 + (tx << 2)] = o;
    }
}

// ---------------- point branch GEMM: pbuf[b][n][co] = wp @ features + bp ----------------
__global__ __launch_bounds__(256) void pgemm_kernel(
    const float* __restrict__ feat,   // [B][64][N]
    const float* __restrict__ wpt,    // [ci][co]
    const float* __restrict__ bp,
    float* __restrict__ pbuf) {
    __shared__ float As[16][136];
    __shared__ float Bs[16][64];
    int tile = blockIdx.x;      // B * (NP/128)
    int b  = tile >> 8;
    int n0 = (tile & 255) << 7;
    int tid = threadIdx.x;
    int tx = tid & 15, ty = tid >> 4;
    int cil = tid >> 4, rg = tid & 15;

    float acc[8][4];
#pragma unroll
    for (int i = 0; i < 8; i++)
#pragma unroll
        for (int j = 0; j < 4; j++) acc[i][j] = 0.f;

    for (int c0 = 0; c0 < 64; c0 += 16) {
        {
            int r  = tid >> 4;
            int cg = (tid & 15) << 2;
            *(float4*)&Bs[r][cg] = *(const float4*)&wpt[(size_t)(c0 + r) * 64 + cg];
        }
        const float* src = feat + ((size_t)(b * 64 + c0 + cil)) * NP_ + n0 + rg * 8;
        *(float4*)&As[cil][rg * 8]     = *(const float4*)&src[0];
        *(float4*)&As[cil][rg * 8 + 4] = *(const float4*)&src[4];
        __syncthreads();

#pragma unroll
        for (int kk = 0; kk < 16; kk++) {
            float4 a0 = *(const float4*)&As[kk][ty << 3];
            float4 a1 = *(const float4*)&As[kk][(ty << 3) + 4];
            float4 bv = *(const float4*)&Bs[kk][tx << 2];
            float a[8] = {a0.x, a0.y, a0.z, a0.w, a1.x, a1.y, a1.z, a1.w};
            float bb[4] = {bv.x, bv.y, bv.z, bv.w};
#pragma unroll
            for (int i = 0; i < 8; i++)
#pragma unroll
                for (int j = 0; j < 4; j++) acc[i][j] += a[i] * bb[j];
        }
        __syncthreads();
    }

    float4 b4 = *(const float4*)&bp[tx << 2];
    size_t obase = ((size_t)b * NP_ + n0) * 64;
#pragma unroll
    for (int i = 0; i < 8; i++) {
        float4 o;
        o.x = acc[i][0] + b4.x;
        o.y = acc[i][1] + b4.y;
        o.z = acc[i][2] + b4.z;
        o.w = acc[i][3] + b4.w;
        *(float4*)&pbuf[obase + (size_t)((ty << 3) + i) * 64 + (tx << 2)] = o;
    }
}

// ---------------- per-channel sum / sumsq over channels-last rows ----------------
__global__ void bnstats_kernel(const float* __restrict__ x, int rows,
                               float* __restrict__ sum, float* __restrict__ sumsq) {
    int co = threadIdx.x & 63;
    int lg = threadIdx.x >> 6;  // 0..3
    float s = 0.f, q = 0.f;
    for (int r = blockIdx.x * 4 + lg; r < rows; r += gridDim.x * 4) {
        float v = x[(size_t)r * 64 + co];
        s += v; q += v * v;
    }
    __shared__ float ss[4][64], qq[4][64];
    ss[lg][co] = s; qq[lg][co] = q;
    __syncthreads();
    if (threadIdx.x < 64) {
        atomicAdd(&sum[co],   ss[0][co] + ss[1][co] + ss[2][co] + ss[3][co]);
        atomicAdd(&sumsq[co], qq[0][co] + qq[1][co] + qq[2][co] + qq[3][co]);
    }
}

__global__ void bnfinal_kernel(const float* __restrict__ sum, const float* __restrict__ sumsq,
                               const float* __restrict__ g, const float* __restrict__ be,
                               float inv_rows, float* __restrict__ scale, float* __restrict__ shift) {
    int c = threadIdx.x;
    float mu  = sum[c] * inv_rows;
    float var = sumsq[c] * inv_rows - mu * mu;
    float sc  = g[c] * rsqrtf(var + 1e-4f);
    scale[c] = sc;
    shift[c] = be[c] - mu * sc;
}

// ---------------- devoxelize + point branch + output transpose ----------------
__global__ __launch_bounds__(128) void final_kernel(
    const float* __restrict__ grid,   // conv2 out [b][vox][64] (raw, BN applied here)
    const float* __restrict__ nc,     // [b][3][N]
    const float* __restrict__ pbuf,   // [b][n][64]
    const float* __restrict__ bn,     // [6][64]
    float* __restrict__ out) {        // [B][64][N]
    __shared__ float stile[64][33];
    int blk = blockIdx.x;             // B * (NP/32)
    int b  = blk >> 10;
    int n0 = (blk & 1023) << 5;
    int tid = threadIdx.x;
    int p = tid & 31, q = tid >> 5;   // q: co group of 16
    int n = n0 + p;

    float fx = nc[((size_t)b * 3 + 0) * NP_ + n];
    float fy = nc[((size_t)b * 3 + 1) * NP_ + n];
    float fz = nc[((size_t)b * 3 + 2) * NP_ + n];
    float flx = floorf(fx), fly = floorf(fy), flz = floorf(fz);
    int lx = min(max((int)flx, 0), 31);
    int lyv = min(max((int)fly, 0), 31);
    int lzv = min(max((int)flz, 0), 31);
    int hx = min(lx + 1, 31), hy = min(lyv + 1, 31), hz = min(lzv + 1, 31);
    float frx = fx - flx, fry = fy - fly, frz = fz - flz;

    const float* s2 = bn + 2 * 64;
    const float* h2 = bn + 3 * 64;
    const float* sp = bn + 4 * 64;
    const float* hp = bn + 5 * 64;

    float res[16];
    {
        const float* pb = pbuf + ((size_t)b * NP_ + n) * 64 + q * 16;
#pragma unroll
        for (int i = 0; i < 16; i++) {
            float tv = pb[i] * sp[q * 16 + i] + hp[q * 16 + i];
            res[i] = fmaxf(tv, 0.f);
        }
    }
#pragma unroll
    for (int c = 0; c < 8; c++) {
        int ix = (c & 4) ? hx : lx;
        int iy = (c & 2) ? hy : lyv;
        int iz = (c & 1) ? hz : lzv;
        float w = ((c & 4) ? frx : 1.f - frx) *
                  ((c & 2) ? fry : 1.f - fry) *
                  ((c & 1) ? frz : 1.f - frz);
        const float* g = grid + ((size_t)b * R3_ + (size_t)(ix * 1024 + iy * 32 + iz)) * 64 + q * 16;
#pragma unroll
        for (int i = 0; i < 16; i++) {
            float tv = g[i] * s2[q * 16 + i] + h2[q * 16 + i];
            res[i] += w * fmaxf(tv, 0.1f * tv);
        }
    }
#pragma unroll
    for (int i = 0; i < 16; i++) stile[q * 16 + i][p] = res[i];
    __syncthreads();
    for (int r = tid >> 5; r < 64; r += 4)
        out[((size_t)b * 64 + r) * NP_ + n0 + p] = stile[r][p];
}

// ---------------- launch ----------------
extern "C" void kernel_launch(void* const* d_in, const int* in_sizes, int n_in,
                              void* d_out, int out_size) {
    const float* features = (const float*)d_in[0];
    const float* coords   = (const float*)d_in[1];
    const float* w1  = (const float*)d_in[2];
    const float* b1  = (const float*)d_in[3];
    const float* g1  = (const float*)d_in[4];
    const float* be1 = (const float*)d_in[5];
    const float* w2  = (const float*)d_in[6];
    const float* b2  = (const float*)d_in[7];
    const float* g2  = (const float*)d_in[8];
    const float* be2 = (const float*)d_in[9];
    const float* wp  = (const float*)d_in[10];
    const float* bp  = (const float*)d_in[11];
    const float* gp  = (const float*)d_in[12];
    const float* bep = (const float*)d_in[13];
    float* out = (float*)d_out;

    float *p_grid0, *p_conv1, *p_conv2, *p_pbuf, *p_nc, *p_wt1, *p_wt2, *p_wpt, *p_stats, *p_bn;
    cudaGetSymbolAddress((void**)&p_grid0, g_grid0);
    cudaGetSymbolAddress((void**)&p_conv1, g_conv1);
    cudaGetSymbolAddress((void**)&p_conv2, g_conv2);
    cudaGetSymbolAddress((void**)&p_pbuf,  g_pbuf);
    cudaGetSymbolAddress((void**)&p_nc,    g_nc);
    cudaGetSymbolAddress((void**)&p_wt1,   g_wt1);
    cudaGetSymbolAddress((void**)&p_wt2,   g_wt2);
    cudaGetSymbolAddress((void**)&p_wpt,   g_wpt);
    cudaGetSymbolAddress((void**)&p_stats, g_stats);
    cudaGetSymbolAddress((void**)&p_bn,    g_bn);

    const int conv_rows  = B_ * R3_;   // 262144
    const int point_rows = B_ * NP_;   // 262144

    zero_kernel<<<(B_ * R3_ * C_) / 256, 256>>>();
    prep_kernel<<<(27 * 64 * 64 + 255) / 256, 256>>>(w1, w2, wp);
    mean_kernel<<<B_, 256>>>(coords);
    maxnorm_kernel<<<B_, 256>>>(coords);
    voxelidx_kernel<<<(B_ * NP_) / 256, 256>>>(coords);
    scatter_kernel<<<(B_ * 64 * NP_) / 256, 256>>>(features);
    avg_kernel<<<(B_ * R3_ * 64) / 256, 256>>>();

    conv3d_kernel<<<B_ * 256, 256>>>(p_grid0, p_conv1, p_wt1, b1, nullptr, nullptr);
    bnstats_kernel<<<512, 256>>>(p_conv1, conv_rows, p_stats + 0, p_stats + 64);
    bnfinal_kernel<<<1, 64>>>(p_stats + 0, p_stats + 64, g1, be1,
                              1.f / (float)conv_rows, p_bn + 0, p_bn + 64);

    conv3d_kernel<<<B_ * 256, 256>>>(p_conv1, p_conv2, p_wt2, b2, p_bn + 0, p_bn + 64);
    bnstats_kernel<<<512, 256>>>(p_conv2, conv_rows, p_stats + 128, p_stats + 192);
    bnfinal_kernel<<<1, 64>>>(p_stats + 128, p_stats + 192, g2, be2,
                              1.f / (float)conv_rows, p_bn + 128, p_bn + 192);

    pgemm_kernel<<<B_ * 256, 256>>>(features, p_wpt, bp, p_pbuf);
    bnstats_kernel<<<512, 256>>>(p_pbuf, point_rows, p_stats + 256, p_stats + 320);
    bnfinal_kernel<<<1, 64>>>(p_stats + 256, p_stats + 320, gp, bep,
                              1.f / (float)point_rows, p_bn + 256, p_bn + 320);

    final_kernel<<<B_ * NP_ / 32, 128>>>(p_conv2, p_nc, p_pbuf, p_bn, out);
}